// round 6
// baseline (speedup 1.0000x reference)
#include <cuda_runtime.h>
#include <stdint.h>

#define B_IMG   64
#define M_GT    100
#define N_PROP  4000
#define K_TOT   (N_PROP + M_GT)   // 4100
#define NUM_CLASSES 80
#define BATCH   512
#define NFG_TGT 128
#define HBINS   1024
#define CAP     2048
#define NEED_FG 128
#define NEED_BG 512

#define T1      512               // match_kernel threads
#define S_SLICES 9                // ceil(4100/512)
#define T2      1024              // sample_kernel threads

typedef unsigned long long ull;

// __device__ scratch (allocation-free rule). g_hist invariant: all-zero at
// kernel_launch entry (zero-init at load; sample_kernel re-zeroes after read),
// so graph replays are deterministic.
__device__ ull   g_keys[B_IMG * K_TOT];
__device__ float g_mval[B_IMG * K_TOT];
__device__ int   g_midx[B_IMG * K_TOT];
__device__ int   g_hist[B_IMG * 2 * HBINS];   // [img][fg|bg][bin]

// ================= Kernel 1: IoU matching + keys + histograms ====================
__global__ __launch_bounds__(T1)
void match_kernel(const float* __restrict__ gt_boxes,
                  const float* __restrict__ prop_boxes,
                  const float* __restrict__ rand_pri)
{
    __shared__ float4 sgtb[M_GT];
    __shared__ float  sgta[M_GT];
    __shared__ int    shist[2 * HBINS];

    const int c     = blockIdx.x;
    const int img   = c / S_SLICES;
    const int slice = c % S_SLICES;
    const int tid   = threadIdx.x;

    const float* gtb = gt_boxes + (size_t)img * M_GT * 4;

    if (tid < M_GT) {
        float4 bx = *reinterpret_cast<const float4*>(gtb + tid * 4);
        sgtb[tid] = bx;
        sgta[tid] = (bx.z - bx.x) * (bx.w - bx.y);
    }
    for (int i = tid; i < 2 * HBINS; i += T1) shist[i] = 0;
    __syncthreads();

    const int k = slice * T1 + tid;
    if (k < K_TOT) {
        float4 bx;
        if (k < N_PROP)
            bx = *reinterpret_cast<const float4*>(prop_boxes + ((size_t)img * N_PROP + k) * 4);
        else
            bx = sgtb[k - N_PROP];
        const float area_b = (bx.z - bx.x) * (bx.w - bx.y);

        // division-free argmax via cross-multiplication; first-max preserved
        float best_i = -1.0f, best_u = 1.0f;
        int   bi = 0;
        #pragma unroll 4
        for (int m = 0; m < M_GT; m++) {
            float4 g = sgtb[m];
            float w = fminf(g.z, bx.z) - fmaxf(g.x, bx.x);
            float h = fminf(g.w, bx.w) - fmaxf(g.y, bx.y);
            w = fmaxf(w, 0.0f);
            h = fmaxf(h, 0.0f);
            float inter = w * h;                        // >= 0
            float uni   = (sgta[m] + area_b) - inter;   // > 0
            if (inter * best_u > best_i * uni) {
                best_i = inter; best_u = uni; bi = m;
            }
        }
        float mval = best_i / best_u;       // one exact IEEE divide
        bool  fg   = (mval >= 0.5f);

        const size_t gk = (size_t)img * K_TOT + k;
        g_mval[gk] = mval;
        g_midx[gk] = bi;

        float p = rand_pri[gk];             // [0,1): float bits monotone as uint
        unsigned int key32 = __float_as_uint(p);
        if (fg) key32 |= 0x80000000u;
        g_keys[gk] = ((ull)key32 << 32) | (unsigned int)k;

        int bin = min(HBINS - 1, (int)(p * (float)HBINS));
        atomicAdd(&shist[(fg ? 0 : HBINS) + bin], 1);
    }
    __syncthreads();

    int* gh = g_hist + (size_t)img * 2 * HBINS;
    for (int i = tid; i < 2 * HBINS; i += T1) {
        int v = shist[i];
        if (v) atomicAdd(&gh[i], v);
    }
}

// ================= Kernel 2: scan + select + rank-scatter + emit =================
__global__ __launch_bounds__(T2)
void sample_kernel(const int* __restrict__ gt_classes,
                   float* __restrict__ out,
                   int sec_stride)
{
    __shared__ int sfxf[HBINS];
    __shared__ int sfxb[HBINS];
    __shared__ int wtf[32], wtb[32];      // warp totals
    __shared__ int wsf[32], wsb[32];      // warp suffix totals
    __shared__ ull cand[CAP];
    __shared__ int t_fg, t_bg, ncand;

    const int b    = blockIdx.x;
    const int tid  = threadIdx.x;
    const int lane = tid & 31;
    const int warp = tid >> 5;

    int* gh = g_hist + (size_t)b * 2 * HBINS;
    int vf = gh[tid];
    int vb = gh[HBINS + tid];
    gh[tid] = 0;                // restore all-zero invariant for next replay
    gh[HBINS + tid] = 0;

    if (tid == 0) { t_fg = 0; t_bg = 0; ncand = 0; }

    // intra-warp suffix sums (lane L gets sum of lanes >= L)
    #pragma unroll
    for (int off = 1; off < 32; off <<= 1) {
        int of = __shfl_down_sync(0xffffffffu, vf, off);
        int ob = __shfl_down_sync(0xffffffffu, vb, off);
        if (lane + off < 32) { vf += of; vb += ob; }
    }
    if (lane == 0) { wtf[warp] = vf; wtb[warp] = vb; }
    __syncthreads();
    if (warp == 0) {
        int tf = wtf[lane], tb = wtb[lane];
        #pragma unroll
        for (int off = 1; off < 32; off <<= 1) {
            int of = __shfl_down_sync(0xffffffffu, tf, off);
            int ob = __shfl_down_sync(0xffffffffu, tb, off);
            if (lane + off < 32) { tf += of; tb += ob; }
        }
        wsf[lane] = tf;
        wsb[lane] = tb;
    }
    __syncthreads();
    int sf = vf + ((warp < 31) ? wsf[warp + 1] : 0);  // suffix count, bins >= tid
    int sb = vb + ((warp < 31) ? wsb[warp + 1] : 0);
    sfxf[tid] = sf;
    sfxb[tid] = sb;
    __syncthreads();

    // cutoffs (unique crossing of non-increasing suffix)
    {
        int sfn = (tid < HBINS - 1) ? sfxf[tid + 1] : 0;
        if (sf >= NEED_FG && sfn < NEED_FG) t_fg = tid;
        int sbn = (tid < HBINS - 1) ? sfxb[tid + 1] : 0;
        if (sb >= NEED_BG && sbn < NEED_BG) t_bg = tid;
    }
    __syncthreads();

    // gather candidates (superset of reference top-k per group)
    const int tfg = t_fg, tbg = t_bg;
    const ull* keys = g_keys + (size_t)b * K_TOT;
    for (int k = tid; k < K_TOT; k += T2) {
        ull key = keys[k];
        bool fg = (key >> 63) != 0ull;
        float p = __uint_as_float((unsigned int)(key >> 32) & 0x7fffffffu);
        int bin = min(HBINS - 1, (int)(p * (float)HBINS));
        if (bin >= (fg ? tfg : tbg)) {
            int pos = atomicAdd(&ncand, 1);
            if (pos < CAP) cand[pos] = key;
        }
    }
    __syncthreads();

    const int nc      = min(ncand, CAP);
    const int cfg     = sfxf[0];          // total fg
    const int cand_fg = sfxf[tfg];        // fg candidates (rank block length)
    const int num_fg  = min(NFG_TGT, cfg);
    const int cbg     = K_TOT - cfg;
    const int num_bg  = min(BATCH - num_fg, cbg);
    const int nvalid  = num_fg + num_bg;

    const int*   gcls = gt_classes + (size_t)b * M_GT;
    const float* mv   = g_mval + (size_t)b * K_TOT;
    const int*   mi_g = g_midx + (size_t)b * K_TOT;

    float* o_iou = out + 0 * (size_t)sec_stride + (size_t)b * BATCH;
    float* o_idx = out + 1 * (size_t)sec_stride + (size_t)b * BATCH;
    float* o_cls = out + 2 * (size_t)sec_stride + (size_t)b * BATCH;
    float* o_gt  = out + 3 * (size_t)sec_stride + (size_t)b * BATCH;
    float* o_val = out + 4 * (size_t)sec_stride + (size_t)b * BATCH;

    // rank-scatter: each candidate's descending rank = #larger keys (keys unique)
    for (int i = tid; i < nc; i += T2) {
        ull me = cand[i];
        int r = 0;
        for (int j = 0; j < nc; j++) r += (cand[j] > me) ? 1 : 0;

        bool fg = (me >> 63) != 0ull;
        int p = -1;
        if (fg) {
            if (r < num_fg) p = r;                       // fg block: ranks [0, cand_fg)
        } else {
            int rb = r - cand_fg;                        // bg rank within bg block
            if (rb < num_bg) p = num_fg + rb;
        }
        if (p >= 0) {
            int idx = (int)(me & 0xffffffffull);
            int mi  = mi_g[idx];
            o_iou[p] = mv[idx];
            o_idx[p] = (float)idx;
            o_cls[p] = fg ? (float)gcls[mi] : (float)NUM_CLASSES;
            o_gt[p]  = (float)mi;
            o_val[p] = 1.0f;
        }
    }

    // defaults for invalid tail (disjoint positions -> no race with scatter)
    for (int p = nvalid + tid; p < BATCH; p += T2) {
        o_iou[p] = 0.0f;
        o_idx[p] = -1.0f;
        o_cls[p] = -1.0f;
        o_gt[p]  = -1.0f;
        o_val[p] = 0.0f;
    }
}

extern "C" void kernel_launch(void* const* d_in, const int* in_sizes, int n_in,
                              void* d_out, int out_size) {
    const float* gt_boxes   = (const float*)d_in[0];
    const float* prop_boxes = (const float*)d_in[1];
    const int*   gt_classes = (const int*)d_in[2];
    const float* rand_pri   = (const float*)d_in[3];
    float* out = (float*)d_out;

    int sec_stride = out_size / 5;

    match_kernel<<<B_IMG * S_SLICES, T1>>>(gt_boxes, prop_boxes, rand_pri);
    sample_kernel<<<B_IMG, T2>>>(gt_classes, out, sec_stride);
}